// round 12
// baseline (speedup 1.0000x reference)
#include <cuda_runtime.h>

// AnchorLoss: sum over masked pairs of 1 - exp(-||(e_i+a_i)-(e_j+a_j)||^2 / 10)
// B=8, N=2048, D=2. Mandatory traffic: the 134MB int32 mask, read once.
//
// R12 = R11 + two occupancy/latency changes (DRAM 70.9% now dominant):
//  - __launch_bounds__(128,10): regs <=51 -> 40 warps/SM resident (+11% MLP)
//  - mask ring LDGs issued FIRST in the item prologue (DRAM requests in
//    flight while L2-resident point constants are built)
// Core (unchanged from R11):
//  - exponent = w_r + w_c + 2u_r*u_c + 2v_r*v_c; pair = 2xFFMA+MUFU+ISETP+@P FADD
//  - 2^(w_r) factored out per row; row consts via SHFL.IDX from lanes 0..7
//  - item 32 rows x 128 cols, grid 8192; depth-4 register LDG.128 ring, __ldcs

#define BATCH    8
#define NPTS     2048
#define THREADS  128
#define NWARPS   4
#define ROWS_IT  32                      // rows per item/block
#define ROWS_PW  8                       // rows per warp
#define DEPTH    4

__global__ void __launch_bounds__(THREADS, 10) anchor_loss_kernel(
    const float* __restrict__ emb,
    const float* __restrict__ abscoords,
    const int*   __restrict__ mask,
    float*       __restrict__ out)
{
    __shared__ float wsum[NWARPS];

    const int warp = threadIdx.x >> 5;
    const int lane = threadIdx.x & 31;
    const float S = 0.37982354f;         // sqrt(log2(e)/10)

    // 8192 blocks = 8 batches * 16 slabs * 64 row-groups
    const int b   = blockIdx.x >> 10;            // 1024 items per batch
    const int rem = blockIdx.x & 1023;
    const int j0  = (rem >> 6) * 128;            // column slab base
    const int i0  = (rem & 63) * ROWS_IT;        // row-group base

    const float2* e2 = (const float2*)emb       + (size_t)b * NPTS;
    const float2* a2 = (const float2*)abscoords + (size_t)b * NPTS;

    // ---- FIRST: get the DRAM mask stream in flight ----
    const int iA = i0 + warp * ROWS_PW;
    const int4* mrow = reinterpret_cast<const int4*>(
        mask + ((size_t)b * NPTS + iA) * NPTS + j0) + lane;
    // row stride = NPTS ints = 512 int4

    int4 mb[DEPTH];
    #pragma unroll
    for (int d = 0; d < DEPTH; d++)
        mb[d] = __ldcs(mrow + 512 * d);

    // ---- lane's 4 slab-point constants (u, v, w = -(u^2+v^2)) — L2 hits ----
    float u4[4], v4[4], w4[4];
    {
        const float4* ee = reinterpret_cast<const float4*>(e2 + j0);
        const float4* aa = reinterpret_cast<const float4*>(a2 + j0);
        float4 ex0 = __ldg(ee + 2 * lane);
        float4 ex1 = __ldg(ee + 2 * lane + 1);
        float4 ax0 = __ldg(aa + 2 * lane);
        float4 ax1 = __ldg(aa + 2 * lane + 1);
        u4[0] = (ex0.x + ax0.x) * S;  v4[0] = (ex0.y + ax0.y) * S;
        u4[1] = (ex0.z + ax0.z) * S;  v4[1] = (ex0.w + ax0.w) * S;
        u4[2] = (ex1.x + ax1.x) * S;  v4[2] = (ex1.y + ax1.y) * S;
        u4[3] = (ex1.z + ax1.z) * S;  v4[3] = (ex1.w + ax1.w) * S;
        #pragma unroll
        for (int k = 0; k < 4; k++)
            w4[k] = -fmaf(u4[k], u4[k], v4[k] * v4[k]);
    }

    // ---- this warp's 8 row constants, one per lane (lanes 0..7; others dup) ----
    float ru2, rv2, rew;
    {
        const int rl = iA + (lane & (ROWS_PW - 1));
        float2 er = __ldg(e2 + rl);
        float2 ar = __ldg(a2 + rl);
        float u = (er.x + ar.x) * S;
        float v = (er.y + ar.y) * S;
        ru2 = u + u;
        rv2 = v + v;
        float w = -fmaf(u, u, v * v);
        asm("ex2.approx.ftz.f32 %0, %1;" : "=f"(rew) : "f"(w));   // 2^(w_r)
    }

    float es  = 0.0f;
    int   cnt = 0;

    #pragma unroll
    for (int r = 0; r < ROWS_PW; r++) {
        const int4 m = mb[r & (DEPTH - 1)];
        // refill slot with row r+4 (wraps in-bounds on tail; discarded)
        mb[r & (DEPTH - 1)] = __ldcs(mrow + 512 * ((r + DEPTH) & (ROWS_PW - 1)));

        // fetch row constants from the owning lane
        const float u2r = __shfl_sync(0xffffffffu, ru2, r);
        const float v2r = __shfl_sync(0xffffffffu, rv2, r);
        const float ewr = __shfl_sync(0xffffffffu, rew, r);

        float racc = 0.0f;
        float t, ev;

        t = fmaf(u2r, u4[0], w4[0]);
        t = fmaf(v2r, v4[0], t);
        asm("ex2.approx.ftz.f32 %0, %1;" : "=f"(ev) : "f"(t));
        if (m.x) racc += ev;

        t = fmaf(u2r, u4[1], w4[1]);
        t = fmaf(v2r, v4[1], t);
        asm("ex2.approx.ftz.f32 %0, %1;" : "=f"(ev) : "f"(t));
        if (m.y) racc += ev;

        t = fmaf(u2r, u4[2], w4[2]);
        t = fmaf(v2r, v4[2], t);
        asm("ex2.approx.ftz.f32 %0, %1;" : "=f"(ev) : "f"(t));
        if (m.z) racc += ev;

        t = fmaf(u2r, u4[3], w4[3]);
        t = fmaf(v2r, v4[3], t);
        asm("ex2.approx.ftz.f32 %0, %1;" : "=f"(ev) : "f"(t));
        if (m.w) racc += ev;

        es = fmaf(racc, ewr, es);            // row partial * 2^(w_r)
        cnt += (m.x + m.y) + (m.z + m.w);    // mask values are 0/1
    }

    float acc = (float)cnt - es;             // masked sum of (1 - e)

    #pragma unroll
    for (int off = 16; off; off >>= 1)
        acc += __shfl_xor_sync(0xffffffffu, acc, off);
    if (lane == 0) wsum[warp] = acc;
    __syncthreads();

    if (threadIdx.x == 0) {
        float s = 0.0f;
        #pragma unroll
        for (int w = 0; w < NWARPS; w++) s += wsum[w];
        atomicAdd(out, s);
    }
}

extern "C" void kernel_launch(void* const* d_in, const int* in_sizes, int n_in,
                              void* d_out, int out_size)
{
    const float* emb  = (const float*)d_in[0];
    const float* absc = (const float*)d_in[1];
    const int*   mask = (const int*)d_in[2];
    float*       out  = (float*)d_out;

    cudaMemsetAsync(out, 0, sizeof(float));

    dim3 grid(BATCH * 1024);   // 8192 one-item blocks
    anchor_loss_kernel<<<grid, THREADS>>>(emb, absc, mask, out);
}